// round 1
// baseline (speedup 1.0000x reference)
#include <cuda_runtime.h>
#include <math.h>

#define NATOMS 5000
#define NPAIRS 160000
#define KCH 128
#define FEAT 1152               /* 9 * 128 */
#define MS 0.1767767f           /* MSG_SCALE */
#define ISC 0.2f                /* INIT_SCALE */
#define SQ3 1.7320508075688772f

__device__ float g_feats[NATOMS * FEAT];
__device__ float g_new[NATOMS * FEAT];

__device__ __forceinline__ float siluf(float x) { return x / (1.f + expf(-x)); }

/* ---------------- zero / copy ---------------- */
__global__ void zero_kernel() {
    int n = NATOMS * FEAT;
    for (int i = blockIdx.x * blockDim.x + threadIdx.x; i < n; i += gridDim.x * blockDim.x)
        g_feats[i] = 0.f;
}
__global__ void copy_kernel() {
    int n = NATOMS * FEAT;
    for (int i = blockIdx.x * blockDim.x + threadIdx.x; i < n; i += gridDim.x * blockDim.x)
        g_new[i] = g_feats[i];
}

/* ---------------- pair message kernels ----------------
 * warp-per-pair (grid-stride). lane computes h[lane] of the radial hidden
 * layer, h broadcast via shfl; lane accumulates 12 of the 384 layer-2 outputs
 * (o = lane + 32t) so that lane owns R[l][k] for k % 32 == lane.
 * w2 (32x384) staged once per block in 48KB shared.
 */
template <int PASS>
__global__ __launch_bounds__(256)
void pair_kernel(const float* __restrict__ pos, const float* __restrict__ cells,
                 const int* __restrict__ species, const int* __restrict__ shifts,
                 const int* __restrict__ ctr, const int* __restrict__ nbr,
                 const int* __restrict__ spair, const float* __restrict__ embed,
                 const float* __restrict__ w1, const float* __restrict__ b1,
                 const float* __restrict__ w2, const float* __restrict__ b2)
{
    __shared__ float w2s[12288];
    for (int i = threadIdx.x; i < 12288; i += blockDim.x) w2s[i] = w2[i];
    __syncthreads();

    const int lane = threadIdx.x & 31;
    const int warp0 = (blockIdx.x * blockDim.x + threadIdx.x) >> 5;
    const int nw = (gridDim.x * blockDim.x) >> 5;

    for (int p = warp0; p < NPAIRS; p += nw) {
        const int c = __ldg(ctr + p);
        const int n = __ldg(nbr + p);
        const int s = __ldg(spair + p);
        const float sx = (float)__ldg(shifts + 3 * p + 0) - 1.f;
        const float sy = (float)__ldg(shifts + 3 * p + 1) - 1.f;
        const float sz = (float)__ldg(shifts + 3 * p + 2) - 1.f;
        const float* M = cells + 9 * s;
        float vx = __ldg(pos + 3 * n + 0) - __ldg(pos + 3 * c + 0) + sx * __ldg(M + 0) + sy * __ldg(M + 3) + sz * __ldg(M + 6);
        float vy = __ldg(pos + 3 * n + 1) - __ldg(pos + 3 * c + 1) + sx * __ldg(M + 1) + sy * __ldg(M + 4) + sz * __ldg(M + 7);
        float vz = __ldg(pos + 3 * n + 2) - __ldg(pos + 3 * c + 2) + sx * __ldg(M + 2) + sy * __ldg(M + 5) + sz * __ldg(M + 8);
        const float dd = vx * vx + vy * vy + vz * vz + 1e-12f;
        const float d = sqrtf(dd);
        const float id = 1.f / d;
        const float x = vx * id, y = vy * id, z = vz * id;
        /* scaled spherical harmonics, comps 0..8 */
        float sh[9];
        sh[0] = ISC;
        sh[1] = ISC * y; sh[2] = ISC * z; sh[3] = ISC * x;
        sh[4] = ISC * SQ3 * x * y;
        sh[5] = ISC * SQ3 * y * z;
        sh[6] = ISC * 0.5f * (3.f * z * z - 1.f);
        sh[7] = ISC * SQ3 * x * z;
        sh[8] = ISC * 0.5f * SQ3 * (x * x - y * y);

        /* radial basis * cutoff */
        const float fc = (d < 5.f) ? 0.5f * (cosf(0.6283185307179586f * d) + 1.f) : 0.f;
        float in[8];
#pragma unroll
        for (int b = 0; b < 8; b++) {
            float t = d - 0.7142857142857143f * (float)b;
            in[b] = expf(-2.f * t * t) * fc;
        }
        /* hidden layer: lane owns h[lane] */
        float hacc = __ldg(b1 + lane);
#pragma unroll
        for (int b = 0; b < 8; b++) hacc += in[b] * __ldg(w1 + b * 32 + lane);
        const float hown = siluf(hacc);

        /* layer 2: lane accumulates outputs o = lane + 32t, t=0..11 */
        float R[12];
#pragma unroll
        for (int t = 0; t < 12; t++) R[t] = __ldg(b2 + lane + 32 * t);
#pragma unroll 4
        for (int b = 0; b < 32; b++) {
            const float hb = __shfl_sync(0xffffffffu, hown, b);
            const float* wrow = w2s + b * 384 + lane;
#pragma unroll
            for (int t = 0; t < 12; t++) R[t] += hb * wrow[32 * t];
        }

        if (PASS == 1) {
            const float* emb = embed + __ldg(species + n) * KCH;
            float* fb = g_feats + c * FEAT;
#pragma unroll
            for (int t = 0; t < 4; t++) {
                const int k = lane + 32 * t;
                const float e = __ldg(emb + k) * MS;
                const float t0 = R[t] * e, t1 = R[4 + t] * e, t2 = R[8 + t] * e;
                atomicAdd(fb + 0 * KCH + k, sh[0] * t0);
                atomicAdd(fb + 1 * KCH + k, sh[1] * t1);
                atomicAdd(fb + 2 * KCH + k, sh[2] * t1);
                atomicAdd(fb + 3 * KCH + k, sh[3] * t1);
                atomicAdd(fb + 4 * KCH + k, sh[4] * t2);
                atomicAdd(fb + 5 * KCH + k, sh[5] * t2);
                atomicAdd(fb + 6 * KCH + k, sh[6] * t2);
                atomicAdd(fb + 7 * KCH + k, sh[7] * t2);
                atomicAdd(fb + 8 * KCH + k, sh[8] * t2);
            }
        } else {
            const float* gn = g_feats + n * FEAT;
            float* fb = g_new + c * FEAT;
#pragma unroll
            for (int t = 0; t < 4; t++) {
                const int k = lane + 32 * t;
                const float r0 = R[t] * MS, r1 = R[4 + t] * MS, r2 = R[8 + t] * MS;
                const float inv = __ldg(gn + k);
                const float u1 = r1 * inv, u2 = r2 * inv;
                atomicAdd(fb + k, sh[0] * r0 * inv + r0 * inv);
                atomicAdd(fb + 1 * KCH + k, sh[1] * u1 + r0 * __ldg(gn + 1 * KCH + k));
                atomicAdd(fb + 2 * KCH + k, sh[2] * u1 + r0 * __ldg(gn + 2 * KCH + k));
                atomicAdd(fb + 3 * KCH + k, sh[3] * u1 + r0 * __ldg(gn + 3 * KCH + k));
                atomicAdd(fb + 4 * KCH + k, sh[4] * u2 + r0 * __ldg(gn + 4 * KCH + k));
                atomicAdd(fb + 5 * KCH + k, sh[5] * u2 + r0 * __ldg(gn + 5 * KCH + k));
                atomicAdd(fb + 6 * KCH + k, sh[6] * u2 + r0 * __ldg(gn + 6 * KCH + k));
                atomicAdd(fb + 7 * KCH + k, sh[7] * u2 + r0 * __ldg(gn + 7 * KCH + k));
                atomicAdd(fb + 8 * KCH + k, sh[8] * u2 + r0 * __ldg(gn + 8 * KCH + k));
            }
        }
    }
}

/* ---------------- CG tensor-square iterate (per atom, per k) ---------------- */
template <int BUF>
__global__ __launch_bounds__(128)
void cg_kernel(const float* __restrict__ mix, const float* __restrict__ U2g)
{
    __shared__ float U[81];
    const int k = threadIdx.x;
    if (k < 81) U[k] = U2g[k];
    __syncthreads();
    float* F = (BUF == 0) ? g_feats : g_new;
    float* base = F + blockIdx.x * FEAT + k;

    /* l = 0 */
    const float f0 = base[0];
    base[0] = f0 + __ldg(mix + k) * f0 * f0;

    /* l = 1, offset 1 in the 9-vector */
    {
        float f1[3];
#pragma unroll
        for (int j = 0; j < 3; j++) f1[j] = base[(1 + j) * KCH];
        float Mv[9];
#pragma unroll
        for (int q = 0; q < 9; q++)
            Mv[q] = U[9 + q] * f1[0] + U[18 + q] * f1[1] + U[27 + q] * f1[2];
        float Cm[9];
#pragma unroll
        for (int i = 0; i < 3; i++)
#pragma unroll
            for (int j = 0; j < 3; j++)
                Cm[3 * i + j] = Mv[3 * i] * Mv[j] + Mv[3 * i + 1] * Mv[3 + j] + Mv[3 * i + 2] * Mv[6 + j];
        const float m1 = __ldg(mix + KCH + k);
        float B[9];
#pragma unroll
        for (int q = 0; q < 9; q++) B[q] = Mv[q] + m1 * Cm[q];
#pragma unroll
        for (int j = 0; j < 3; j++) {
            float o = 0.f;
#pragma unroll
            for (int q = 0; q < 9; q++) o += U[(1 + j) * 9 + q] * B[q];
            base[(1 + j) * KCH] = o;
        }
    }
    /* l = 2, offset 4 */
    {
        float f2[5];
#pragma unroll
        for (int j = 0; j < 5; j++) f2[j] = base[(4 + j) * KCH];
        float Mv[9];
#pragma unroll
        for (int q = 0; q < 9; q++)
            Mv[q] = U[36 + q] * f2[0] + U[45 + q] * f2[1] + U[54 + q] * f2[2] + U[63 + q] * f2[3] + U[72 + q] * f2[4];
        float Cm[9];
#pragma unroll
        for (int i = 0; i < 3; i++)
#pragma unroll
            for (int j = 0; j < 3; j++)
                Cm[3 * i + j] = Mv[3 * i] * Mv[j] + Mv[3 * i + 1] * Mv[3 + j] + Mv[3 * i + 2] * Mv[6 + j];
        const float m2 = __ldg(mix + 2 * KCH + k);
        float B[9];
#pragma unroll
        for (int q = 0; q < 9; q++) B[q] = Mv[q] + m2 * Cm[q];
#pragma unroll
        for (int j = 0; j < 5; j++) {
            float o = 0.f;
#pragma unroll
            for (int q = 0; q < 9; q++) o += U[(4 + j) * 9 + q] * B[q];
            base[(4 + j) * KCH] = o;
        }
    }
}

/* ---------------- head MLP ---------------- */
__global__ __launch_bounds__(128)
void head_kernel(const float* __restrict__ hw1, const float* __restrict__ hb1,
                 const float* __restrict__ hw2, const float* __restrict__ hb2,
                 const float* __restrict__ lw, const float* __restrict__ lb,
                 float* __restrict__ out)
{
    const int a = blockIdx.x, j = threadIdx.x;
    __shared__ float hs[128];
    __shared__ float red[4];
    hs[j] = g_new[a * FEAT + j];   /* feats[0][:,0,:] */
    __syncthreads();
    float acc = __ldg(hb1 + j);
#pragma unroll 8
    for (int k2 = 0; k2 < 128; k2++) acc += hs[k2] * __ldg(hw1 + k2 * 128 + j);
    float v = siluf(acc);
    __syncthreads();
    hs[j] = v;
    __syncthreads();
    acc = __ldg(hb2 + j);
#pragma unroll 8
    for (int k2 = 0; k2 < 128; k2++) acc += hs[k2] * __ldg(hw2 + k2 * 128 + j);
    v = siluf(acc);
    float part = v * __ldg(lw + j);
#pragma unroll
    for (int o = 16; o > 0; o >>= 1) part += __shfl_down_sync(0xffffffffu, part, o);
    if ((j & 31) == 0) red[j >> 5] = part;
    __syncthreads();
    if (j == 0) out[a] = red[0] + red[1] + red[2] + red[3] + __ldg(lb);
}

extern "C" void kernel_launch(void* const* d_in, const int* in_sizes, int n_in,
                              void* d_out, int out_size)
{
    const float* pos     = (const float*)d_in[0];
    const float* cells   = (const float*)d_in[1];
    const int*   species = (const int*)d_in[2];
    const int*   shifts  = (const int*)d_in[3];
    const int*   ctr     = (const int*)d_in[4];
    const int*   nbr     = (const int*)d_in[5];
    const int*   spair   = (const int*)d_in[6];
    const float* embed   = (const float*)d_in[7];
    const float* rw1 = (const float*)d_in[8];
    const float* rb1 = (const float*)d_in[9];
    const float* rw2 = (const float*)d_in[10];
    const float* rb2 = (const float*)d_in[11];
    const float* ew1 = (const float*)d_in[12];
    const float* eb1 = (const float*)d_in[13];
    const float* ew2 = (const float*)d_in[14];
    const float* eb2 = (const float*)d_in[15];
    const float* mixa  = (const float*)d_in[16];
    const float* emixa = (const float*)d_in[17];
    const float* hw1 = (const float*)d_in[18];
    const float* hb1 = (const float*)d_in[19];
    const float* hw2 = (const float*)d_in[20];
    const float* hb2 = (const float*)d_in[21];
    const float* lw  = (const float*)d_in[22];
    const float* lb  = (const float*)d_in[23];
    const float* U2  = (const float*)d_in[24];
    float* out = (float*)d_out;

    zero_kernel<<<2048, 256>>>();
    pair_kernel<1><<<592, 256>>>(pos, cells, species, shifts, ctr, nbr, spair,
                                 embed, rw1, rb1, rw2, rb2);
    cg_kernel<0><<<NATOMS, 128>>>(mixa, U2);
    copy_kernel<<<2048, 256>>>();
    pair_kernel<2><<<592, 256>>>(pos, cells, species, shifts, ctr, nbr, spair,
                                 embed, ew1, eb1, ew2, eb2);
    cg_kernel<1><<<NATOMS, 128>>>(emixa, U2);
    head_kernel<<<NATOMS, 128>>>(hw1, hb1, hw2, hb2, lw, lb, out);
}

// round 2
// speedup vs baseline: 1.5078x; 1.5078x over previous
#include <cuda_runtime.h>
#include <math.h>

#define NATOMS 5000
#define NPAIRS 160000
#define KCH 128
#define FEAT 1152               /* 9 * 128 */
#define MS 0.1767767f           /* MSG_SCALE */
#define ISC 0.2f                /* INIT_SCALE */
#define SQ3 1.7320508075688772f

__device__ float g_feats[NATOMS * FEAT];
__device__ float g_new[NATOMS * FEAT];

__device__ __forceinline__ float siluf(float x) { return x / (1.f + expf(-x)); }

typedef unsigned long long u64;
__device__ __forceinline__ u64 pk2(float lo, float hi) {
    u64 r; asm("mov.b64 %0,{%1,%2};" : "=l"(r) : "f"(lo), "f"(hi)); return r;
}
__device__ __forceinline__ void upk2(float& lo, float& hi, u64 v) {
    asm("mov.b64 {%0,%1},%2;" : "=f"(lo), "=f"(hi) : "l"(v));
}
__device__ __forceinline__ void fma2(u64& d, u64 a, u64 b) {
    asm("fma.rn.f32x2 %0,%1,%2,%0;" : "+l"(d) : "l"(a), "l"(b));
}

/* ---------------- zero (float4) ---------------- */
__global__ void zero_kernel() {
    float4* p = (float4*)g_feats;
    const int n = NATOMS * FEAT / 4;
    for (int i = blockIdx.x * blockDim.x + threadIdx.x; i < n; i += gridDim.x * blockDim.x)
        p[i] = make_float4(0.f, 0.f, 0.f, 0.f);
}

/* ---------------- pair message kernels ----------------
 * warp processes 4 pairs per iteration. lane owns hidden unit h[lane] for all
 * 4 pairs; layer-2 GEMM uses packed fma.rn.f32x2 over pair-pairs so one w2
 * shared load + pack feeds 4 MACs. Outputs o = lane + 32t, t=0..11.
 */
template <int PASS>
__global__ __launch_bounds__(128)
void pair_kernel(const float* __restrict__ pos, const float* __restrict__ cells,
                 const int* __restrict__ species, const int* __restrict__ shifts,
                 const int* __restrict__ ctr, const int* __restrict__ nbr,
                 const int* __restrict__ spair, const float* __restrict__ embed,
                 const float* __restrict__ w1, const float* __restrict__ b1,
                 const float* __restrict__ w2, const float* __restrict__ b2)
{
    __shared__ float w2s[12288];
    {
        float4* d4 = (float4*)w2s;
        const float4* s4 = (const float4*)w2;
        for (int i = threadIdx.x; i < 3072; i += 128) d4[i] = s4[i];
    }
    __syncthreads();

    const int lane = threadIdx.x & 31;
    const int warp0 = (blockIdx.x * 128 + threadIdx.x) >> 5;
    const int nw = (gridDim.x * 128) >> 5;

    for (int g4 = warp0; g4 < NPAIRS / 4; g4 += nw) {
        const int p0 = g4 * 4;
        int ci[4], ni[4];
        float sh[9][4];
        float hac[4];
#pragma unroll
        for (int pp = 0; pp < 4; pp++) {
            const int p = p0 + pp;
            const int c = __ldg(ctr + p);
            const int n = __ldg(nbr + p);
            const int s = __ldg(spair + p);
            ci[pp] = c; ni[pp] = n;
            const float sx = (float)__ldg(shifts + 3 * p + 0) - 1.f;
            const float sy = (float)__ldg(shifts + 3 * p + 1) - 1.f;
            const float sz = (float)__ldg(shifts + 3 * p + 2) - 1.f;
            const float* M = cells + 9 * s;
            float vx = __ldg(pos + 3 * n + 0) - __ldg(pos + 3 * c + 0) + sx * __ldg(M + 0) + sy * __ldg(M + 3) + sz * __ldg(M + 6);
            float vy = __ldg(pos + 3 * n + 1) - __ldg(pos + 3 * c + 1) + sx * __ldg(M + 1) + sy * __ldg(M + 4) + sz * __ldg(M + 7);
            float vz = __ldg(pos + 3 * n + 2) - __ldg(pos + 3 * c + 2) + sx * __ldg(M + 2) + sy * __ldg(M + 5) + sz * __ldg(M + 8);
            const float dd = vx * vx + vy * vy + vz * vz + 1e-12f;
            const float d = sqrtf(dd);
            const float id = 1.f / d;
            const float x = vx * id, y = vy * id, z = vz * id;
            sh[0][pp] = ISC;
            sh[1][pp] = ISC * y; sh[2][pp] = ISC * z; sh[3][pp] = ISC * x;
            sh[4][pp] = ISC * SQ3 * x * y;
            sh[5][pp] = ISC * SQ3 * y * z;
            sh[6][pp] = ISC * 0.5f * (3.f * z * z - 1.f);
            sh[7][pp] = ISC * SQ3 * x * z;
            sh[8][pp] = ISC * 0.5f * SQ3 * (x * x - y * y);

            const float fc = (d < 5.f) ? 0.5f * (cosf(0.6283185307179586f * d) + 1.f) : 0.f;
            float hacc = __ldg(b1 + lane);
#pragma unroll
            for (int b = 0; b < 8; b++) {
                float t = d - 0.7142857142857143f * (float)b;
                hacc += expf(-2.f * t * t) * fc * __ldg(w1 + b * 32 + lane);
            }
            hac[pp] = siluf(hacc);
        }

        /* layer 2: packed accumulators, Ra = pairs(0,1), Rb = pairs(2,3) */
        u64 Ra[12], Rb[12];
#pragma unroll
        for (int t = 0; t < 12; t++) {
            const float bv = __ldg(b2 + lane + 32 * t);
            Ra[t] = pk2(bv, bv);
            Rb[t] = Ra[t];
        }
#pragma unroll 2
        for (int b = 0; b < 32; b++) {
            const float h0 = __shfl_sync(0xffffffffu, hac[0], b);
            const float h1 = __shfl_sync(0xffffffffu, hac[1], b);
            const float h2 = __shfl_sync(0xffffffffu, hac[2], b);
            const float h3 = __shfl_sync(0xffffffffu, hac[3], b);
            const u64 hb01 = pk2(h0, h1);
            const u64 hb23 = pk2(h2, h3);
            const float* wrow = w2s + b * 384 + lane;
#pragma unroll
            for (int t = 0; t < 12; t++) {
                const float w = wrow[32 * t];
                const u64 wv = pk2(w, w);
                fma2(Ra[t], wv, hb01);
                fma2(Rb[t], wv, hb23);
            }
        }

        /* epilogue per pair */
#pragma unroll
        for (int pp = 0; pp < 4; pp++) {
            float R[12];
#pragma unroll
            for (int t = 0; t < 12; t++) {
                float lo, hi;
                upk2(lo, hi, (pp < 2) ? Ra[t] : Rb[t]);
                R[t] = (pp & 1) ? hi : lo;
            }
            const int c = ci[pp], n = ni[pp];
            if (PASS == 1) {
                const float* emb = embed + __ldg(species + n) * KCH;
                float* fb = g_feats + c * FEAT;
#pragma unroll
                for (int t = 0; t < 4; t++) {
                    const int k = lane + 32 * t;
                    const float e = __ldg(emb + k) * MS;
                    const float t0 = R[t] * e, t1 = R[4 + t] * e, t2 = R[8 + t] * e;
                    atomicAdd(fb + 0 * KCH + k, sh[0][pp] * t0);
                    atomicAdd(fb + 1 * KCH + k, sh[1][pp] * t1);
                    atomicAdd(fb + 2 * KCH + k, sh[2][pp] * t1);
                    atomicAdd(fb + 3 * KCH + k, sh[3][pp] * t1);
                    atomicAdd(fb + 4 * KCH + k, sh[4][pp] * t2);
                    atomicAdd(fb + 5 * KCH + k, sh[5][pp] * t2);
                    atomicAdd(fb + 6 * KCH + k, sh[6][pp] * t2);
                    atomicAdd(fb + 7 * KCH + k, sh[7][pp] * t2);
                    atomicAdd(fb + 8 * KCH + k, sh[8][pp] * t2);
                }
            } else {
                const float* gn = g_feats + n * FEAT;
                float* fb = g_new + c * FEAT;
#pragma unroll
                for (int t = 0; t < 4; t++) {
                    const int k = lane + 32 * t;
                    const float r0 = R[t] * MS, r1 = R[4 + t] * MS, r2 = R[8 + t] * MS;
                    const float inv = __ldg(gn + k);
                    const float u1 = r1 * inv, u2 = r2 * inv;
                    atomicAdd(fb + k, sh[0][pp] * r0 * inv + r0 * inv);
                    atomicAdd(fb + 1 * KCH + k, sh[1][pp] * u1 + r0 * __ldg(gn + 1 * KCH + k));
                    atomicAdd(fb + 2 * KCH + k, sh[2][pp] * u1 + r0 * __ldg(gn + 2 * KCH + k));
                    atomicAdd(fb + 3 * KCH + k, sh[3][pp] * u1 + r0 * __ldg(gn + 3 * KCH + k));
                    atomicAdd(fb + 4 * KCH + k, sh[4][pp] * u2 + r0 * __ldg(gn + 4 * KCH + k));
                    atomicAdd(fb + 5 * KCH + k, sh[5][pp] * u2 + r0 * __ldg(gn + 5 * KCH + k));
                    atomicAdd(fb + 6 * KCH + k, sh[6][pp] * u2 + r0 * __ldg(gn + 6 * KCH + k));
                    atomicAdd(fb + 7 * KCH + k, sh[7][pp] * u2 + r0 * __ldg(gn + 7 * KCH + k));
                    atomicAdd(fb + 8 * KCH + k, sh[8][pp] * u2 + r0 * __ldg(gn + 8 * KCH + k));
                }
            }
        }
    }
}

/* ---------------- CG tensor-square iterate (per atom, per k) ----------------
 * BUF==0: read/write g_feats AND duplicate result into g_new (replaces copy).
 * BUF==1: read/write g_new.
 */
template <int BUF>
__global__ __launch_bounds__(128)
void cg_kernel(const float* __restrict__ mix, const float* __restrict__ U2g)
{
    __shared__ float U[81];
    const int k = threadIdx.x;
    if (k < 81) U[k] = U2g[k];
    __syncthreads();
    float* base = ((BUF == 0) ? g_feats : g_new) + blockIdx.x * FEAT + k;
    float* dup  = g_new + blockIdx.x * FEAT + k;

    /* l = 0 */
    {
        const float f0 = base[0];
        const float v = f0 + __ldg(mix + k) * f0 * f0;
        base[0] = v;
        if (BUF == 0) dup[0] = v;
    }
    /* l = 1, offset 1 */
    {
        float f1[3];
#pragma unroll
        for (int j = 0; j < 3; j++) f1[j] = base[(1 + j) * KCH];
        float Mv[9];
#pragma unroll
        for (int q = 0; q < 9; q++)
            Mv[q] = U[9 + q] * f1[0] + U[18 + q] * f1[1] + U[27 + q] * f1[2];
        float Cm[9];
#pragma unroll
        for (int i = 0; i < 3; i++)
#pragma unroll
            for (int j = 0; j < 3; j++)
                Cm[3 * i + j] = Mv[3 * i] * Mv[j] + Mv[3 * i + 1] * Mv[3 + j] + Mv[3 * i + 2] * Mv[6 + j];
        const float m1 = __ldg(mix + KCH + k);
        float B[9];
#pragma unroll
        for (int q = 0; q < 9; q++) B[q] = Mv[q] + m1 * Cm[q];
#pragma unroll
        for (int j = 0; j < 3; j++) {
            float o = 0.f;
#pragma unroll
            for (int q = 0; q < 9; q++) o += U[(1 + j) * 9 + q] * B[q];
            base[(1 + j) * KCH] = o;
            if (BUF == 0) dup[(1 + j) * KCH] = o;
        }
    }
    /* l = 2, offset 4 */
    {
        float f2[5];
#pragma unroll
        for (int j = 0; j < 5; j++) f2[j] = base[(4 + j) * KCH];
        float Mv[9];
#pragma unroll
        for (int q = 0; q < 9; q++)
            Mv[q] = U[36 + q] * f2[0] + U[45 + q] * f2[1] + U[54 + q] * f2[2] + U[63 + q] * f2[3] + U[72 + q] * f2[4];
        float Cm[9];
#pragma unroll
        for (int i = 0; i < 3; i++)
#pragma unroll
            for (int j = 0; j < 3; j++)
                Cm[3 * i + j] = Mv[3 * i] * Mv[j] + Mv[3 * i + 1] * Mv[3 + j] + Mv[3 * i + 2] * Mv[6 + j];
        const float m2 = __ldg(mix + 2 * KCH + k);
        float B[9];
#pragma unroll
        for (int q = 0; q < 9; q++) B[q] = Mv[q] + m2 * Cm[q];
#pragma unroll
        for (int j = 0; j < 5; j++) {
            float o = 0.f;
#pragma unroll
            for (int q = 0; q < 9; q++) o += U[(4 + j) * 9 + q] * B[q];
            base[(4 + j) * KCH] = o;
            if (BUF == 0) dup[(4 + j) * KCH] = o;
        }
    }
}

/* ---------------- head MLP: 20 atoms per block, weight reuse ---------------- */
#define APB 20
__global__ __launch_bounds__(128)
void head_kernel(const float* __restrict__ hw1, const float* __restrict__ hb1,
                 const float* __restrict__ hw2, const float* __restrict__ hb2,
                 const float* __restrict__ lw, const float* __restrict__ lb,
                 float* __restrict__ out)
{
    __shared__ float hs[APB][132];
    const int a0 = blockIdx.x * APB;
    const int j = threadIdx.x;

    for (int i = 0; i < APB; i++) hs[i][j] = g_new[(a0 + i) * FEAT + j];
    __syncthreads();

    float acc[APB];
    {
        const float b = __ldg(hb1 + j);
#pragma unroll
        for (int i = 0; i < APB; i++) acc[i] = b;
    }
    for (int kk = 0; kk < 128; kk++) {
        const float w = __ldg(hw1 + kk * 128 + j);
#pragma unroll
        for (int i = 0; i < APB; i++) acc[i] += hs[i][kk] * w;
    }
    __syncthreads();
#pragma unroll
    for (int i = 0; i < APB; i++) hs[i][j] = siluf(acc[i]);
    __syncthreads();
    {
        const float b = __ldg(hb2 + j);
#pragma unroll
        for (int i = 0; i < APB; i++) acc[i] = b;
    }
    for (int kk = 0; kk < 128; kk++) {
        const float w = __ldg(hw2 + kk * 128 + j);
#pragma unroll
        for (int i = 0; i < APB; i++) acc[i] += hs[i][kk] * w;
    }
    __syncthreads();
    {
        const float lwj = __ldg(lw + j);
#pragma unroll
        for (int i = 0; i < APB; i++) hs[i][j] = siluf(acc[i]) * lwj;
    }
    __syncthreads();
    if (j < APB) {
        float s = __ldg(lb);
        for (int q = 0; q < 128; q++) s += hs[j][q];
        out[a0 + j] = s;
    }
}

extern "C" void kernel_launch(void* const* d_in, const int* in_sizes, int n_in,
                              void* d_out, int out_size)
{
    const float* pos     = (const float*)d_in[0];
    const float* cells   = (const float*)d_in[1];
    const int*   species = (const int*)d_in[2];
    const int*   shifts  = (const int*)d_in[3];
    const int*   ctr     = (const int*)d_in[4];
    const int*   nbr     = (const int*)d_in[5];
    const int*   spair   = (const int*)d_in[6];
    const float* embed   = (const float*)d_in[7];
    const float* rw1 = (const float*)d_in[8];
    const float* rb1 = (const float*)d_in[9];
    const float* rw2 = (const float*)d_in[10];
    const float* rb2 = (const float*)d_in[11];
    const float* ew1 = (const float*)d_in[12];
    const float* eb1 = (const float*)d_in[13];
    const float* ew2 = (const float*)d_in[14];
    const float* eb2 = (const float*)d_in[15];
    const float* mixa  = (const float*)d_in[16];
    const float* emixa = (const float*)d_in[17];
    const float* hw1 = (const float*)d_in[18];
    const float* hb1 = (const float*)d_in[19];
    const float* hw2 = (const float*)d_in[20];
    const float* hb2 = (const float*)d_in[21];
    const float* lw  = (const float*)d_in[22];
    const float* lb  = (const float*)d_in[23];
    const float* U2  = (const float*)d_in[24];
    float* out = (float*)d_out;

    zero_kernel<<<1024, 256>>>();
    pair_kernel<1><<<592, 128>>>(pos, cells, species, shifts, ctr, nbr, spair,
                                 embed, rw1, rb1, rw2, rb2);
    cg_kernel<0><<<NATOMS, 128>>>(mixa, U2);
    pair_kernel<2><<<592, 128>>>(pos, cells, species, shifts, ctr, nbr, spair,
                                 embed, ew1, eb1, ew2, eb2);
    cg_kernel<1><<<NATOMS, 128>>>(emixa, U2);
    head_kernel<<<NATOMS / APB, 128>>>(hw1, hb1, hw2, hb2, lw, lb, out);
}

// round 3
// speedup vs baseline: 1.7395x; 1.1537x over previous
#include <cuda_runtime.h>
#include <math.h>

#define NATOMS 5000
#define NPAIRS 160000
#define KCH 128
#define FEAT 1152               /* 9 * 128 */
#define MS 0.1767767f           /* MSG_SCALE */
#define ISC 0.2f                /* INIT_SCALE */
#define SQ3 1.7320508075688772f

__device__ float g_feats[NATOMS * FEAT];
__device__ float g_new[NATOMS * FEAT];
__device__ float4 g_rec[NPAIRS * 4];   /* sorted pair records, 64B each */
__device__ int g_cnt[NATOMS];
__device__ int g_off[NATOMS];

__device__ __forceinline__ float siluf(float x) { return x / (1.f + expf(-x)); }

typedef unsigned long long u64;
__device__ __forceinline__ u64 pk2(float lo, float hi) {
    u64 r; asm("mov.b64 %0,{%1,%2};" : "=l"(r) : "f"(lo), "f"(hi)); return r;
}
__device__ __forceinline__ void upk2(float& lo, float& hi, u64 v) {
    asm("mov.b64 {%0,%1},%2;" : "=f"(lo), "=f"(hi) : "l"(v));
}
__device__ __forceinline__ void fma2(u64& d, u64 a, u64 b) {
    asm("fma.rn.f32x2 %0,%1,%2,%0;" : "+l"(d) : "l"(a), "l"(b));
}

/* ---------------- zero feats + counters ---------------- */
__global__ void zero_kernel() {
    float4* p = (float4*)g_feats;
    const int n = NATOMS * FEAT / 4;
    const int tid = blockIdx.x * blockDim.x + threadIdx.x;
    for (int i = tid; i < n; i += gridDim.x * blockDim.x)
        p[i] = make_float4(0.f, 0.f, 0.f, 0.f);
    if (tid < NATOMS) g_cnt[tid] = 0;
}

/* ---------------- counting sort: hist / scan / scatter+geometry ------------ */
__global__ void hist_kernel(const int* __restrict__ ctr) {
    int p = blockIdx.x * blockDim.x + threadIdx.x;
    if (p < NPAIRS) atomicAdd(&g_cnt[__ldg(ctr + p)], 1);
}

__global__ __launch_bounds__(1024)
void scan_kernel() {
    __shared__ int wsum[32];
    const int t = threadIdx.x;
    const int base = t * 5;
    int c[5]; int s = 0;
#pragma unroll
    for (int i = 0; i < 5; i++) {
        int idx = base + i;
        c[i] = (idx < NATOMS) ? g_cnt[idx] : 0;
        s += c[i];
    }
    const int lane = t & 31, wid = t >> 5;
    int v = s;
#pragma unroll
    for (int o = 1; o < 32; o <<= 1) {
        int u = __shfl_up_sync(0xffffffffu, v, o);
        if (lane >= o) v += u;
    }
    if (lane == 31) wsum[wid] = v;
    __syncthreads();
    if (wid == 0) {
        int w = wsum[lane];
#pragma unroll
        for (int o = 1; o < 32; o <<= 1) {
            int u = __shfl_up_sync(0xffffffffu, w, o);
            if (lane >= o) w += u;
        }
        wsum[lane] = w;
    }
    __syncthreads();
    int excl = v - s + ((wid > 0) ? wsum[wid - 1] : 0);
#pragma unroll
    for (int i = 0; i < 5; i++) {
        int idx = base + i;
        if (idx < NATOMS) { g_off[idx] = excl; excl += c[i]; }
    }
}

__global__ void scatter_kernel(const float* __restrict__ pos, const float* __restrict__ cells,
                               const int* __restrict__ species, const int* __restrict__ shifts,
                               const int* __restrict__ ctr, const int* __restrict__ nbr,
                               const int* __restrict__ spair)
{
    const int p = blockIdx.x * blockDim.x + threadIdx.x;
    if (p >= NPAIRS) return;
    const int c = __ldg(ctr + p);
    const int n = __ldg(nbr + p);
    const int s = __ldg(spair + p);
    const float sx = (float)__ldg(shifts + 3 * p + 0) - 1.f;
    const float sy = (float)__ldg(shifts + 3 * p + 1) - 1.f;
    const float sz = (float)__ldg(shifts + 3 * p + 2) - 1.f;
    const float* M = cells + 9 * s;
    float vx = __ldg(pos + 3 * n + 0) - __ldg(pos + 3 * c + 0) + sx * __ldg(M + 0) + sy * __ldg(M + 3) + sz * __ldg(M + 6);
    float vy = __ldg(pos + 3 * n + 1) - __ldg(pos + 3 * c + 1) + sx * __ldg(M + 1) + sy * __ldg(M + 4) + sz * __ldg(M + 7);
    float vz = __ldg(pos + 3 * n + 2) - __ldg(pos + 3 * c + 2) + sx * __ldg(M + 2) + sy * __ldg(M + 5) + sz * __ldg(M + 8);
    const float dd = vx * vx + vy * vy + vz * vz + 1e-12f;
    const float d = sqrtf(dd);
    const float id = 1.f / d;
    const float fc = (d < 5.f) ? 0.5f * (cosf(0.6283185307179586f * d) + 1.f) : 0.f;
    float in[8];
#pragma unroll
    for (int b = 0; b < 8; b++) {
        float t = d - 0.7142857142857143f * (float)b;
        in[b] = expf(-2.f * t * t) * fc;
    }
    const int dst = atomicAdd(&g_off[c], 1);
    float4* r = g_rec + dst * 4;
    r[0] = make_float4(__int_as_float(c), __int_as_float(n), __int_as_float(__ldg(species + n)), d);
    r[1] = make_float4(vx * id, vy * id, vz * id, 0.f);
    r[2] = make_float4(in[0], in[1], in[2], in[3]);
    r[3] = make_float4(in[4], in[5], in[6], in[7]);
}

/* ---------------- pair message kernels (sorted records) ---------------- */
template <int PASS>
__global__ __launch_bounds__(256, 3)
void pair_kernel(const float* __restrict__ embed,
                 const float* __restrict__ w1, const float* __restrict__ b1,
                 const float* __restrict__ w2, const float* __restrict__ b2)
{
    __shared__ float w2s[12288];
    __shared__ float w1s[256];
    __shared__ float b1s[32];
    __shared__ float b2s[384];
    {
        float4* d4 = (float4*)w2s;
        const float4* s4 = (const float4*)w2;
        for (int i = threadIdx.x; i < 3072; i += 256) d4[i] = s4[i];
        if (threadIdx.x < 256) w1s[threadIdx.x] = w1[threadIdx.x];
        if (threadIdx.x < 32) b1s[threadIdx.x] = b1[threadIdx.x];
        if (threadIdx.x >= 64 && threadIdx.x < 64 + 384) b2s[threadIdx.x - 64] = b2[threadIdx.x - 64];
    }
    __syncthreads();

    const int lane = threadIdx.x & 31;
    const int warp0 = (blockIdx.x * 256 + threadIdx.x) >> 5;
    const int nw = (gridDim.x * 256) >> 5;

    for (int g4 = warp0; g4 < NPAIRS / 4; g4 += nw) {
        /* hidden layer per pair */
        float hac[4];
#pragma unroll
        for (int pp = 0; pp < 4; pp++) {
            const float4* r = g_rec + (g4 * 4 + pp) * 4;
            const float4 i0 = __ldg(r + 2);
            const float4 i1 = __ldg(r + 3);
            float hacc = b1s[lane];
            hacc += i0.x * w1s[0 * 32 + lane];
            hacc += i0.y * w1s[1 * 32 + lane];
            hacc += i0.z * w1s[2 * 32 + lane];
            hacc += i0.w * w1s[3 * 32 + lane];
            hacc += i1.x * w1s[4 * 32 + lane];
            hacc += i1.y * w1s[5 * 32 + lane];
            hacc += i1.z * w1s[6 * 32 + lane];
            hacc += i1.w * w1s[7 * 32 + lane];
            hac[pp] = siluf(hacc);
        }

        /* layer-2 GEMM: packed f32x2, Ra = pairs(0,1), Rb = pairs(2,3) */
        u64 Ra[12], Rb[12];
#pragma unroll
        for (int t = 0; t < 12; t++) {
            const float bv = b2s[lane + 32 * t];
            Ra[t] = pk2(bv, bv);
            Rb[t] = Ra[t];
        }
#pragma unroll 2
        for (int b = 0; b < 32; b++) {
            const float h0 = __shfl_sync(0xffffffffu, hac[0], b);
            const float h1 = __shfl_sync(0xffffffffu, hac[1], b);
            const float h2 = __shfl_sync(0xffffffffu, hac[2], b);
            const float h3 = __shfl_sync(0xffffffffu, hac[3], b);
            const u64 hb01 = pk2(h0, h1);
            const u64 hb23 = pk2(h2, h3);
            const float* wrow = w2s + b * 384 + lane;
#pragma unroll
            for (int t = 0; t < 12; t++) {
                const float w = wrow[32 * t];
                const u64 wv = pk2(w, w);
                fma2(Ra[t], wv, hb01);
                fma2(Rb[t], wv, hb23);
            }
        }

        /* epilogue: reload small record head, merge messages if same center */
        int c_[4], n_[4], sp_[4];
        float xs[4], ys[4], zs[4];
#pragma unroll
        for (int pp = 0; pp < 4; pp++) {
            const float4* r = g_rec + (g4 * 4 + pp) * 4;
            const float4 a = __ldg(r + 0);
            const float4 u = __ldg(r + 1);
            c_[pp] = __float_as_int(a.x);
            n_[pp] = __float_as_int(a.y);
            sp_[pp] = __float_as_int(a.z);
            xs[pp] = u.x; ys[pp] = u.y; zs[pp] = u.z;
        }
        const bool same = (c_[0] == c_[1]) && (c_[1] == c_[2]) && (c_[2] == c_[3]);

#define RG(pp, tt) ({ float _lo, _hi; upk2(_lo, _hi, ((pp) < 2) ? Ra[tt] : Rb[tt]); ((pp) & 1) ? _hi : _lo; })

        if (PASS == 1) {
            if (same) {
                float* fb = g_feats + c_[0] * FEAT;
#pragma unroll
                for (int t = 0; t < 4; t++) {
                    const int k = lane + 32 * t;
                    float a0 = 0, a1 = 0, a2 = 0, a3 = 0, a4 = 0, a5 = 0, a6 = 0, a7 = 0, a8 = 0;
#pragma unroll
                    for (int pp = 0; pp < 4; pp++) {
                        const float e = __ldg(embed + sp_[pp] * KCH + k) * MS;
                        const float r0 = RG(pp, t) * e, r1 = RG(pp, 4 + t) * e, r2 = RG(pp, 8 + t) * e;
                        const float x = xs[pp], y = ys[pp], z = zs[pp];
                        a0 += ISC * r0;
                        a1 += ISC * y * r1; a2 += ISC * z * r1; a3 += ISC * x * r1;
                        a4 += ISC * SQ3 * x * y * r2;
                        a5 += ISC * SQ3 * y * z * r2;
                        a6 += ISC * 0.5f * (3.f * z * z - 1.f) * r2;
                        a7 += ISC * SQ3 * x * z * r2;
                        a8 += ISC * 0.5f * SQ3 * (x * x - y * y) * r2;
                    }
                    atomicAdd(fb + 0 * KCH + k, a0);
                    atomicAdd(fb + 1 * KCH + k, a1);
                    atomicAdd(fb + 2 * KCH + k, a2);
                    atomicAdd(fb + 3 * KCH + k, a3);
                    atomicAdd(fb + 4 * KCH + k, a4);
                    atomicAdd(fb + 5 * KCH + k, a5);
                    atomicAdd(fb + 6 * KCH + k, a6);
                    atomicAdd(fb + 7 * KCH + k, a7);
                    atomicAdd(fb + 8 * KCH + k, a8);
                }
            } else {
#pragma unroll
                for (int pp = 0; pp < 4; pp++) {
                    float* fb = g_feats + c_[pp] * FEAT;
                    const float x = xs[pp], y = ys[pp], z = zs[pp];
#pragma unroll
                    for (int t = 0; t < 4; t++) {
                        const int k = lane + 32 * t;
                        const float e = __ldg(embed + sp_[pp] * KCH + k) * MS;
                        const float r0 = RG(pp, t) * e, r1 = RG(pp, 4 + t) * e, r2 = RG(pp, 8 + t) * e;
                        atomicAdd(fb + 0 * KCH + k, ISC * r0);
                        atomicAdd(fb + 1 * KCH + k, ISC * y * r1);
                        atomicAdd(fb + 2 * KCH + k, ISC * z * r1);
                        atomicAdd(fb + 3 * KCH + k, ISC * x * r1);
                        atomicAdd(fb + 4 * KCH + k, ISC * SQ3 * x * y * r2);
                        atomicAdd(fb + 5 * KCH + k, ISC * SQ3 * y * z * r2);
                        atomicAdd(fb + 6 * KCH + k, ISC * 0.5f * (3.f * z * z - 1.f) * r2);
                        atomicAdd(fb + 7 * KCH + k, ISC * SQ3 * x * z * r2);
                        atomicAdd(fb + 8 * KCH + k, ISC * 0.5f * SQ3 * (x * x - y * y) * r2);
                    }
                }
            }
        } else {
            if (same) {
                float* fb = g_new + c_[0] * FEAT;
#pragma unroll
                for (int t = 0; t < 4; t++) {
                    const int k = lane + 32 * t;
                    float a0 = 0, a1 = 0, a2 = 0, a3 = 0, a4 = 0, a5 = 0, a6 = 0, a7 = 0, a8 = 0;
#pragma unroll
                    for (int pp = 0; pp < 4; pp++) {
                        const float* gn = g_feats + n_[pp] * FEAT;
                        const float r0 = RG(pp, t) * MS, r1 = RG(pp, 4 + t) * MS, r2 = RG(pp, 8 + t) * MS;
                        const float inv = __ldg(gn + k);
                        const float x = xs[pp], y = ys[pp], z = zs[pp];
                        const float u1 = r1 * inv, u2 = r2 * inv;
                        a0 += ISC * r0 * inv + r0 * inv;
                        a1 += ISC * y * u1 + r0 * __ldg(gn + 1 * KCH + k);
                        a2 += ISC * z * u1 + r0 * __ldg(gn + 2 * KCH + k);
                        a3 += ISC * x * u1 + r0 * __ldg(gn + 3 * KCH + k);
                        a4 += ISC * SQ3 * x * y * u2 + r0 * __ldg(gn + 4 * KCH + k);
                        a5 += ISC * SQ3 * y * z * u2 + r0 * __ldg(gn + 5 * KCH + k);
                        a6 += ISC * 0.5f * (3.f * z * z - 1.f) * u2 + r0 * __ldg(gn + 6 * KCH + k);
                        a7 += ISC * SQ3 * x * z * u2 + r0 * __ldg(gn + 7 * KCH + k);
                        a8 += ISC * 0.5f * SQ3 * (x * x - y * y) * u2 + r0 * __ldg(gn + 8 * KCH + k);
                    }
                    atomicAdd(fb + 0 * KCH + k, a0);
                    atomicAdd(fb + 1 * KCH + k, a1);
                    atomicAdd(fb + 2 * KCH + k, a2);
                    atomicAdd(fb + 3 * KCH + k, a3);
                    atomicAdd(fb + 4 * KCH + k, a4);
                    atomicAdd(fb + 5 * KCH + k, a5);
                    atomicAdd(fb + 6 * KCH + k, a6);
                    atomicAdd(fb + 7 * KCH + k, a7);
                    atomicAdd(fb + 8 * KCH + k, a8);
                }
            } else {
#pragma unroll
                for (int pp = 0; pp < 4; pp++) {
                    float* fb = g_new + c_[pp] * FEAT;
                    const float* gn = g_feats + n_[pp] * FEAT;
                    const float x = xs[pp], y = ys[pp], z = zs[pp];
#pragma unroll
                    for (int t = 0; t < 4; t++) {
                        const int k = lane + 32 * t;
                        const float r0 = RG(pp, t) * MS, r1 = RG(pp, 4 + t) * MS, r2 = RG(pp, 8 + t) * MS;
                        const float inv = __ldg(gn + k);
                        const float u1 = r1 * inv, u2 = r2 * inv;
                        atomicAdd(fb + k, ISC * r0 * inv + r0 * inv);
                        atomicAdd(fb + 1 * KCH + k, ISC * y * u1 + r0 * __ldg(gn + 1 * KCH + k));
                        atomicAdd(fb + 2 * KCH + k, ISC * z * u1 + r0 * __ldg(gn + 2 * KCH + k));
                        atomicAdd(fb + 3 * KCH + k, ISC * x * u1 + r0 * __ldg(gn + 3 * KCH + k));
                        atomicAdd(fb + 4 * KCH + k, ISC * SQ3 * x * y * u2 + r0 * __ldg(gn + 4 * KCH + k));
                        atomicAdd(fb + 5 * KCH + k, ISC * SQ3 * y * z * u2 + r0 * __ldg(gn + 5 * KCH + k));
                        atomicAdd(fb + 6 * KCH + k, ISC * 0.5f * (3.f * z * z - 1.f) * u2 + r0 * __ldg(gn + 6 * KCH + k));
                        atomicAdd(fb + 7 * KCH + k, ISC * SQ3 * x * z * u2 + r0 * __ldg(gn + 7 * KCH + k));
                        atomicAdd(fb + 8 * KCH + k, ISC * 0.5f * SQ3 * (x * x - y * y) * u2 + r0 * __ldg(gn + 8 * KCH + k));
                    }
                }
            }
        }
#undef RG
    }
}

/* ---------------- CG tensor-square iterate (per atom, per k) ---------------- */
template <int BUF>
__global__ __launch_bounds__(128)
void cg_kernel(const float* __restrict__ mix, const float* __restrict__ U2g)
{
    __shared__ float U[81];
    const int k = threadIdx.x;
    if (k < 81) U[k] = U2g[k];
    __syncthreads();
    float* base = ((BUF == 0) ? g_feats : g_new) + blockIdx.x * FEAT + k;
    float* dup  = g_new + blockIdx.x * FEAT + k;

    {
        const float f0 = base[0];
        const float v = f0 + __ldg(mix + k) * f0 * f0;
        base[0] = v;
        if (BUF == 0) dup[0] = v;
    }
    {
        float f1[3];
#pragma unroll
        for (int j = 0; j < 3; j++) f1[j] = base[(1 + j) * KCH];
        float Mv[9];
#pragma unroll
        for (int q = 0; q < 9; q++)
            Mv[q] = U[9 + q] * f1[0] + U[18 + q] * f1[1] + U[27 + q] * f1[2];
        float Cm[9];
#pragma unroll
        for (int i = 0; i < 3; i++)
#pragma unroll
            for (int j = 0; j < 3; j++)
                Cm[3 * i + j] = Mv[3 * i] * Mv[j] + Mv[3 * i + 1] * Mv[3 + j] + Mv[3 * i + 2] * Mv[6 + j];
        const float m1 = __ldg(mix + KCH + k);
        float B[9];
#pragma unroll
        for (int q = 0; q < 9; q++) B[q] = Mv[q] + m1 * Cm[q];
#pragma unroll
        for (int j = 0; j < 3; j++) {
            float o = 0.f;
#pragma unroll
            for (int q = 0; q < 9; q++) o += U[(1 + j) * 9 + q] * B[q];
            base[(1 + j) * KCH] = o;
            if (BUF == 0) dup[(1 + j) * KCH] = o;
        }
    }
    {
        float f2[5];
#pragma unroll
        for (int j = 0; j < 5; j++) f2[j] = base[(4 + j) * KCH];
        float Mv[9];
#pragma unroll
        for (int q = 0; q < 9; q++)
            Mv[q] = U[36 + q] * f2[0] + U[45 + q] * f2[1] + U[54 + q] * f2[2] + U[63 + q] * f2[3] + U[72 + q] * f2[4];
        float Cm[9];
#pragma unroll
        for (int i = 0; i < 3; i++)
#pragma unroll
            for (int j = 0; j < 3; j++)
                Cm[3 * i + j] = Mv[3 * i] * Mv[j] + Mv[3 * i + 1] * Mv[3 + j] + Mv[3 * i + 2] * Mv[6 + j];
        const float m2 = __ldg(mix + 2 * KCH + k);
        float B[9];
#pragma unroll
        for (int q = 0; q < 9; q++) B[q] = Mv[q] + m2 * Cm[q];
#pragma unroll
        for (int j = 0; j < 5; j++) {
            float o = 0.f;
#pragma unroll
            for (int q = 0; q < 9; q++) o += U[(4 + j) * 9 + q] * B[q];
            base[(4 + j) * KCH] = o;
            if (BUF == 0) dup[(4 + j) * KCH] = o;
        }
    }
}

/* ---------------- head MLP: 20 atoms per block ---------------- */
#define APB 20
__global__ __launch_bounds__(128)
void head_kernel(const float* __restrict__ hw1, const float* __restrict__ hb1,
                 const float* __restrict__ hw2, const float* __restrict__ hb2,
                 const float* __restrict__ lw, const float* __restrict__ lb,
                 float* __restrict__ out)
{
    __shared__ float hs[APB][132];
    const int a0 = blockIdx.x * APB;
    const int j = threadIdx.x;

    for (int i = 0; i < APB; i++) hs[i][j] = g_new[(a0 + i) * FEAT + j];
    __syncthreads();

    float acc[APB];
    {
        const float b = __ldg(hb1 + j);
#pragma unroll
        for (int i = 0; i < APB; i++) acc[i] = b;
    }
    for (int kk = 0; kk < 128; kk++) {
        const float w = __ldg(hw1 + kk * 128 + j);
#pragma unroll
        for (int i = 0; i < APB; i++) acc[i] += hs[i][kk] * w;
    }
    __syncthreads();
#pragma unroll
    for (int i = 0; i < APB; i++) hs[i][j] = siluf(acc[i]);
    __syncthreads();
    {
        const float b = __ldg(hb2 + j);
#pragma unroll
        for (int i = 0; i < APB; i++) acc[i] = b;
    }
    for (int kk = 0; kk < 128; kk++) {
        const float w = __ldg(hw2 + kk * 128 + j);
#pragma unroll
        for (int i = 0; i < APB; i++) acc[i] += hs[i][kk] * w;
    }
    __syncthreads();
    {
        const float lwj = __ldg(lw + j);
#pragma unroll
        for (int i = 0; i < APB; i++) hs[i][j] = siluf(acc[i]) * lwj;
    }
    __syncthreads();
    if (j < APB) {
        float s = __ldg(lb);
        for (int q = 0; q < 128; q++) s += hs[j][q];
        out[a0 + j] = s;
    }
}

extern "C" void kernel_launch(void* const* d_in, const int* in_sizes, int n_in,
                              void* d_out, int out_size)
{
    const float* pos     = (const float*)d_in[0];
    const float* cells   = (const float*)d_in[1];
    const int*   species = (const int*)d_in[2];
    const int*   shifts  = (const int*)d_in[3];
    const int*   ctr     = (const int*)d_in[4];
    const int*   nbr     = (const int*)d_in[5];
    const int*   spair   = (const int*)d_in[6];
    const float* embed   = (const float*)d_in[7];
    const float* rw1 = (const float*)d_in[8];
    const float* rb1 = (const float*)d_in[9];
    const float* rw2 = (const float*)d_in[10];
    const float* rb2 = (const float*)d_in[11];
    const float* ew1 = (const float*)d_in[12];
    const float* eb1 = (const float*)d_in[13];
    const float* ew2 = (const float*)d_in[14];
    const float* eb2 = (const float*)d_in[15];
    const float* mixa  = (const float*)d_in[16];
    const float* emixa = (const float*)d_in[17];
    const float* hw1 = (const float*)d_in[18];
    const float* hb1 = (const float*)d_in[19];
    const float* hw2 = (const float*)d_in[20];
    const float* hb2 = (const float*)d_in[21];
    const float* lw  = (const float*)d_in[22];
    const float* lb  = (const float*)d_in[23];
    const float* U2  = (const float*)d_in[24];
    float* out = (float*)d_out;

    zero_kernel<<<1024, 256>>>();
    hist_kernel<<<(NPAIRS + 255) / 256, 256>>>(ctr);
    scan_kernel<<<1, 1024>>>();
    scatter_kernel<<<(NPAIRS + 255) / 256, 256>>>(pos, cells, species, shifts, ctr, nbr, spair);
    pair_kernel<1><<<444, 256>>>(embed, rw1, rb1, rw2, rb2);
    cg_kernel<0><<<NATOMS, 128>>>(mixa, U2);
    pair_kernel<2><<<444, 256>>>(embed, ew1, eb1, ew2, eb2);
    cg_kernel<1><<<NATOMS, 128>>>(emixa, U2);
    head_kernel<<<NATOMS / APB, 128>>>(hw1, hb1, hw2, hb2, lw, lb, out);
}